// round 13
// baseline (speedup 1.0000x reference)
#include <cuda_runtime.h>
#include <cuda_bf16.h>
#include <cstdint>

// Problem constants
#define BB 2
#define NN 65536
#define CC 256
#define HH 8
#define DD 64
#define SS 64
#define INNERD 512
#define NTOK (BB * NN)      // 131072
#define TOK   64            // tokens per CTA
#define NCTA2 (NTOK / TOK)  // 2048

// smem word offsets/strides (all strides ==8 mod 32 -> conflict-free LDS.64)
#define AST 264
#define BST 72
#define WST 72
#define A0W 0
#define B0W (TOK * AST)                 // 16896 words
#define W0W B0W                         // w aliases B slab (dead after GEMM1)
#define F0W (B0W + 64 * WST)            // + 4608
#define SMEM_WORDS (B0W + 128 * BST)    // 26112
#define SMEM_TOTAL (SMEM_WORDS * 4)     // 104448 bytes -> 2 CTAs/SM

// Device scratch
__device__ __align__(16) float g_Weff[HH][CC][SS];
__device__ __align__(16) float g_beff[HH][SS];
__device__ __align__(16) float g_acc[BB * HH * SS * DD];
__device__ __align__(16) float g_norm[BB * HH * SS];
__device__ __align__(16) float g_Btf[HH * 128 * CC];   // tf32-rounded, k8-permuted B^T images

// ---------------- helpers ----------------
__device__ __forceinline__ uint32_t cvt_tf32(float v) {
    uint32_t r;
    asm("cvt.rna.tf32.f32 %0, %1;" : "=r"(r) : "f"(v));
    return r;
}
__device__ __forceinline__ void mma_tf32(float* c, uint32_t a0, uint32_t a1,
                                         uint32_t a2, uint32_t a3,
                                         uint32_t b0, uint32_t b1) {
    asm volatile(
        "mma.sync.aligned.m16n8k8.row.col.f32.tf32.tf32.f32 "
        "{%0,%1,%2,%3}, {%4,%5,%6,%7}, {%8,%9}, {%0,%1,%2,%3};"
        : "+f"(c[0]), "+f"(c[1]), "+f"(c[2]), "+f"(c[3])
        : "r"(a0), "r"(a1), "r"(a2), "r"(a3), "r"(b0), "r"(b1));
}
__device__ __forceinline__ int perm8(int K) {
    return (K & ~7) | ((K & 3) << 1) | ((K >> 2) & 1);
}

// ---------------------------------------------------------------- zero
__global__ void zero_kernel() {
    int i = blockIdx.x * blockDim.x + threadIdx.x;
    if (i < BB * HH * SS * DD) g_acc[i] = 0.0f;
    if (i < BB * HH * SS)      g_norm[i] = 0.0f;
}

// ------------------------------------------------- precompute Weff/beff
__global__ void precompute_kernel(const float* __restrict__ Wx,
                                  const float* __restrict__ bx,
                                  const float* __restrict__ Wslice,
                                  const float* __restrict__ bslice) {
    int m = blockIdx.x;
    int s = threadIdx.x;
    if (m < HH * CC) {
        int h = m / CC, k = m % CC;
        float a = 0.0f;
#pragma unroll 16
        for (int d = 0; d < DD; d++)
            a += Wx[(size_t)k * INNERD + h * DD + d] * Wslice[d * SS + s];
        g_Weff[h][k][s] = a;
    } else {
        for (int h = 0; h < HH; h++) {
            float a = bslice[s];
            for (int d = 0; d < DD; d++)
                a += bx[h * DD + d] * Wslice[d * SS + s];
            g_beff[h][s] = a;
        }
    }
}

// ---- B^T images [h][n(64 s | 64 d)][K perm8], tf32-rounded
__global__ void build_bt(const float* __restrict__ Wfx) {
    int h = blockIdx.x;
    for (int i = threadIdx.x; i < 128 * 256; i += 256) {
        int n = i >> 8, K = i & 255;
        float v = (n < 64) ? g_Weff[h][K][n]
                           : Wfx[(size_t)K * INNERD + h * DD + (n - 64)];
        g_Btf[(size_t)(h * 128 + n) * 256 + perm8(K)] = __uint_as_float(cvt_tf32(v));
    }
}

// ---------------------------------------------------------------- main
extern __shared__ unsigned char smem[];

__global__ __launch_bounds__(128, 2) void fused_main(
    const float* __restrict__ x,
    const float* __restrict__ bfx,
    const float* __restrict__ temperature)
{
    const int t    = threadIdx.x;
    const int wp   = t >> 5;
    const int lane = t & 31;
    const int g    = lane >> 2;
    const int q    = lane & 3;
    const int wml  = wp & 1;          // m-group (32 tok)
    const int wn   = wp >> 1;         // 0: s-half (n 0..63), 1: d-half
    const int ct   = blockIdx.x;
    const int tok0 = ct * TOK;
    const int b    = ct >> 10;

    uint32_t* smu = (uint32_t*)smem;
    float*    smf = (float*)smem;

    // ---- stage A once: tf32-rounded, k8-permuted (64 rows x 256) ----
    for (int it = 0; it < 32; it++) {
        int idx = it * 128 + t;               // 64 rows x 64 float4
        int row = idx >> 6, c4 = idx & 63;
        float4 v = *(const float4*)&x[((size_t)(tok0 + row)) * CC + c4 * 4];
        uint32_t* d = &smu[A0W + row * AST + (c4 >> 1) * 8 + (c4 & 1)];
        d[0] = cvt_tf32(v.x); d[2] = cvt_tf32(v.y);
        d[4] = cvt_tf32(v.z); d[6] = cvt_tf32(v.w);
    }

    // hoisted row offsets
    const int ar0 = (wml * 32 + g) * AST;          // mt=0 lower
    const int ar1 = ar0 + 8 * AST;                 // mt=0 upper
    const int ar2 = ar0 + 16 * AST;                // mt=1 lower
    const int ar3 = ar0 + 24 * AST;                // mt=1 upper
    const int brow = (wn * 64 + g) * BST + 2 * q;  // + nt*8*BST + ks*8

    for (int h = 0; h < HH; h++) {
        float tmp = temperature[h];
        tmp = fminf(fmaxf(tmp, 0.5f), 5.0f);
        const float invt = __fdividef(1.0f, tmp);
        float bias16[16];
#pragma unroll
        for (int nt = 0; nt < 8; nt++)
#pragma unroll
            for (int e = 0; e < 2; e++)
                bias16[nt * 2 + e] = wn ? bfx[h * DD + nt * 8 + 2 * q + e]
                                        : g_beff[h][nt * 8 + 2 * q + e];

        float c[2][8][4];
#pragma unroll
        for (int i = 0; i < 2; i++)
#pragma unroll
            for (int j = 0; j < 8; j++)
#pragma unroll
                for (int e = 0; e < 4; e++) c[i][j][e] = 0.0f;

        const float* img = g_Btf + (size_t)h * 128 * 256;

        // ============ GEMM1: 4 K-slabs of 64, synchronous staging ============
#pragma unroll
        for (int sl = 0; sl < 4; sl++) {
            __syncthreads();   // protect slab region (B or prior head's w/f) from writers
            // stage B slab [128 n][64 k]
#pragma unroll
            for (int it = 0; it < 16; it++) {
                int idx = it * 128 + t;       // 128 rows x 16 float4
                int row = idx >> 4, c4 = idx & 15;
                float4 v = *(const float4*)&img[(size_t)row * 256 + sl * 64 + c4 * 4];
                *(float4*)&smf[B0W + row * BST + c4 * 4] = v;
            }
            __syncthreads();

#pragma unroll
            for (int ks = 0; ks < 8; ks++) {
                const int kc = sl * 64 + ks * 8 + 2 * q;
                uint2 a00 = *(const uint2*)&smu[A0W + ar0 + kc];
                uint2 a01 = *(const uint2*)&smu[A0W + ar1 + kc];
                uint2 a10 = *(const uint2*)&smu[A0W + ar2 + kc];
                uint2 a11 = *(const uint2*)&smu[A0W + ar3 + kc];
#pragma unroll
                for (int nt = 0; nt < 8; nt++) {
                    uint2 bb = *(const uint2*)&smu[B0W + brow + nt * 8 * BST + ks * 8];
                    mma_tf32(c[0][nt], a00.x, a01.x, a00.y, a01.y, bb.x, bb.y);
                    mma_tf32(c[1][nt], a10.x, a11.x, a10.y, a11.y, bb.x, bb.y);
                }
            }
        }
        __syncthreads();   // slab reads done -> w/f stores may overwrite

        // ============ softmax (s-half warps -> w) / bias+store (d-half -> f) ============
        float nacc0 = 0.0f;  // (unused placeholder to keep reg layout tight)
        (void)nacc0;

        if (wn == 0) {
#pragma unroll
            for (int mt = 0; mt < 2; mt++)
#pragma unroll
                for (int rr = 0; rr < 2; rr++) {
                    const int ptok = perm8(wml * 32 + mt * 16 + g + 8 * rr);
                    float pv[16];
                    float mx = -1e30f;
#pragma unroll
                    for (int nt = 0; nt < 8; nt++)
#pragma unroll
                        for (int e = 0; e < 2; e++) {
                            float p = (c[mt][nt][rr * 2 + e] + bias16[nt * 2 + e]) * invt;
                            pv[nt * 2 + e] = p;
                            mx = fmaxf(mx, p);
                        }
                    mx = fmaxf(mx, __shfl_xor_sync(0xffffffffu, mx, 1));
                    mx = fmaxf(mx, __shfl_xor_sync(0xffffffffu, mx, 2));
                    float sv = 0.0f;
#pragma unroll
                    for (int j = 0; j < 16; j++) { pv[j] = __expf(pv[j] - mx); sv += pv[j]; }
                    sv += __shfl_xor_sync(0xffffffffu, sv, 1);
                    sv += __shfl_xor_sync(0xffffffffu, sv, 2);
                    const float r = __fdividef(1.0f, sv);
#pragma unroll
                    for (int nt = 0; nt < 8; nt++)
#pragma unroll
                        for (int e = 0; e < 2; e++)
                            smu[W0W + (nt * 8 + 2 * q + e) * WST + ptok] =
                                cvt_tf32(pv[nt * 2 + e] * r);
                }
        } else {
#pragma unroll
            for (int mt = 0; mt < 2; mt++)
#pragma unroll
                for (int rr = 0; rr < 2; rr++) {
                    const int ptok = perm8(wml * 32 + mt * 16 + g + 8 * rr);
#pragma unroll
                    for (int nt = 0; nt < 8; nt++)
#pragma unroll
                        for (int e = 0; e < 2; e++)
                            smu[F0W + (nt * 8 + 2 * q + e) * WST + ptok] =
                                cvt_tf32(c[mt][nt][rr * 2 + e] + bias16[nt * 2 + e]);
                }
        }
        __syncthreads();

        // ============ rank update: acc[64 s][64 d] += w^T @ fx (K = 64 tok) ============
        {
            const int wm2 = wp & 1;    // s32 group
            const int wn2 = wp >> 1;   // d32 group
            float racc[2][4][4];
#pragma unroll
            for (int i = 0; i < 2; i++)
#pragma unroll
                for (int j = 0; j < 4; j++)
#pragma unroll
                    for (int e = 0; e < 4; e++) racc[i][j][e] = 0.0f;

#pragma unroll
            for (int ks = 0; ks < 8; ks++) {
                const int kc = ks * 8 + 2 * q;
#pragma unroll
                for (int mt = 0; mt < 2; mt++) {
                    const int r0 = wm2 * 32 + mt * 16 + g;
                    uint2 lo = *(const uint2*)&smu[W0W + r0 * WST + kc];
                    uint2 hi = *(const uint2*)&smu[W0W + (r0 + 8) * WST + kc];
#pragma unroll
                    for (int nt = 0; nt < 4; nt++) {
                        uint2 bb = *(const uint2*)&smu[F0W + (wn2 * 32 + nt * 8 + g) * WST + kc];
                        mma_tf32(racc[mt][nt], lo.x, hi.x, lo.y, hi.y, bb.x, bb.y);
                    }
                }
            }

            const int abase = (b * HH + h) * SS;
#pragma unroll
            for (int mt = 0; mt < 2; mt++)
#pragma unroll
                for (int nt = 0; nt < 4; nt++)
#pragma unroll
                    for (int rr = 0; rr < 2; rr++)
#pragma unroll
                        for (int e = 0; e < 2; e++) {
                            int s = wm2 * 32 + mt * 16 + g + 8 * rr;
                            int d = wn2 * 32 + nt * 8 + 2 * q + e;
                            atomicAdd(&g_acc[(abase + s) * DD + d],
                                      racc[mt][nt][rr * 2 + e]);
                        }
        }

        // ---- norm: row-sums of w (16 rows per warp) ----
        {
            const int nb = (b * HH + h) * SS;
#pragma unroll
            for (int j = 0; j < 16; j++) {
                int s = wp * 16 + j;
                float acc = smf[W0W + s * WST + lane] + smf[W0W + s * WST + lane + 32];
#pragma unroll
                for (int off = 16; off >= 1; off >>= 1)
                    acc += __shfl_xor_sync(0xffffffffu, acc, off);
                if (lane == 0) atomicAdd(&g_norm[nb + s], acc);
            }
        }
        // next head's first slab-stage __syncthreads protects w/f reads
    }
}

// ------------------------------------------------------------ finalize
__global__ void finalize_kernel(float* __restrict__ out) {
    int i = blockIdx.x * blockDim.x + threadIdx.x;
    if (i < BB * HH * SS * DD)
        out[i] = g_acc[i] / (g_norm[i >> 6] + 0.01f);
}

// -------------------------------------------------------------- launch
extern "C" void kernel_launch(void* const* d_in, const int* in_sizes, int n_in,
                              void* d_out, int out_size) {
    const float* x           = (const float*)d_in[0];
    const float* Wx          = (const float*)d_in[1];
    const float* bx          = (const float*)d_in[2];
    const float* Wfx         = (const float*)d_in[3];
    const float* bfx         = (const float*)d_in[4];
    const float* Wslice      = (const float*)d_in[5];
    const float* bslice      = (const float*)d_in[6];
    const float* temperature = (const float*)d_in[7];
    float* out = (float*)d_out;

    cudaFuncSetAttribute(fused_main, cudaFuncAttributeMaxDynamicSharedMemorySize,
                         SMEM_TOTAL);

    zero_kernel<<<(BB * HH * SS * DD + 255) / 256, 256>>>();
    precompute_kernel<<<HH * CC + 1, 64>>>(Wx, bx, Wslice, bslice);
    build_bt<<<HH, 256>>>(Wfx);
    fused_main<<<NCTA2, 128, SMEM_TOTAL>>>(x, bfx, temperature);
    finalize_kernel<<<(BB * HH * SS * DD + 255) / 256, 256>>>(out);
}

// round 15
// speedup vs baseline: 2.0470x; 2.0470x over previous
#include <cuda_runtime.h>
#include <cuda_bf16.h>
#include <cuda_fp16.h>
#include <cstdint>

// Problem constants
#define BB 2
#define NN 65536
#define CC 256
#define HH 8
#define DD 64
#define SS 64
#define INNERD 512
#define NTOK (BB * NN)      // 131072
#define NCTA (NTOK / 128)   // 1024

// smem u32-word offsets/strides (strides ==8 mod 32 -> conflict-free LDS.64)
#define AST 136                       // A row stride (u32; 128 cols + 8 pad)
#define BSTW 72                       // B slab / w / f row stride (u32)
#define A0W 0                         // A: 128 x 136 = 17408 u32
#define B0W 17408                     // B slab: 128 x 72 = 9216 u32
#define W0W B0W                       // w aliases slab (dead after GEMM1)
#define F0W (B0W + 64 * BSTW)         // 22016
#define BSW (B0W + 9216)              // 26624: beff[64] f32
#define BDW (BSW + 64)                // 26688: bfx[64] f32
#define SMEM_TOTAL ((BDW + 64) * 4)   // 107008 bytes -> 2 CTAs/SM

// Device scratch
__device__ __align__(16) float g_Weff[HH][CC][SS];
__device__ __align__(16) float g_beff[HH][SS];
__device__ __align__(16) float g_acc[BB * HH * SS * DD];
__device__ __align__(16) float g_norm[BB * HH * SS];
__device__ __align__(16) uint32_t g_Bh[HH * 128 * 128];  // fp16x2 B^T images, col-permuted

// ---------------- helpers ----------------
// permute u32-cols within 8 so fragment pairs (q, q+4) land at (2q, 2q+1)
__device__ __forceinline__ int permc(int c) {
    return (c & ~7) | ((c & 3) << 1) | ((c >> 2) & 1);
}
__device__ __forceinline__ void mma_f16(float* c, uint32_t a0, uint32_t a1,
                                        uint32_t a2, uint32_t a3,
                                        uint32_t b0, uint32_t b1) {
    asm volatile(
        "mma.sync.aligned.m16n8k16.row.col.f32.f16.f16.f32 "
        "{%0,%1,%2,%3}, {%4,%5,%6,%7}, {%8,%9}, {%0,%1,%2,%3};"
        : "+f"(c[0]), "+f"(c[1]), "+f"(c[2]), "+f"(c[3])
        : "r"(a0), "r"(a1), "r"(a2), "r"(a3), "r"(b0), "r"(b1));
}
__device__ __forceinline__ uint32_t pack2(float lo, float hi) {
    __half2 h = __floats2half2_rn(lo, hi);   // .x = lo -> low 16 bits
    return *reinterpret_cast<uint32_t*>(&h);
}

// ---------------------------------------------------------------- zero
__global__ void zero_kernel() {
    int i = blockIdx.x * blockDim.x + threadIdx.x;
    if (i < BB * HH * SS * DD) g_acc[i] = 0.0f;
    if (i < BB * HH * SS)      g_norm[i] = 0.0f;
}

// ------------------------------------------------- precompute Weff/beff
__global__ void precompute_kernel(const float* __restrict__ Wx,
                                  const float* __restrict__ bx,
                                  const float* __restrict__ Wslice,
                                  const float* __restrict__ bslice) {
    int m = blockIdx.x;
    int s = threadIdx.x;
    if (m < HH * CC) {
        int h = m / CC, k = m % CC;
        float a = 0.0f;
#pragma unroll 16
        for (int d = 0; d < DD; d++)
            a += Wx[(size_t)k * INNERD + h * DD + d] * Wslice[d * SS + s];
        g_Weff[h][k][s] = a;
    } else {
        for (int h = 0; h < HH; h++) {
            float a = bslice[s];
            for (int d = 0; d < DD; d++)
                a += bx[h * DD + d] * Wslice[d * SS + s];
            g_beff[h][s] = a;
        }
    }
}

// ---- B^T images [h][n(64 s | 64 d)][128 u32 cols, permuted], fp16 pairs
__global__ void build_bt(const float* __restrict__ Wfx) {
    int h = blockIdx.x;
    for (int i = threadIdx.x; i < 128 * 128; i += 256) {
        int n = i >> 7, c = i & 127;   // c = u32 col (k pair 2c, 2c+1)
        float v0, v1;
        if (n < 64) {
            v0 = g_Weff[h][2 * c][n];
            v1 = g_Weff[h][2 * c + 1][n];
        } else {
            v0 = Wfx[(size_t)(2 * c)     * INNERD + h * DD + (n - 64)];
            v1 = Wfx[(size_t)(2 * c + 1) * INNERD + h * DD + (n - 64)];
        }
        g_Bh[(h * 128 + n) * 128 + permc(c)] = pack2(v0, v1);
    }
}

// ---------------------------------------------------------------- main
extern __shared__ unsigned char smem[];

__global__ __launch_bounds__(256, 2) void fused_main(
    const float* __restrict__ x,
    const float* __restrict__ bfx,
    const float* __restrict__ temperature)
{
    const int t    = threadIdx.x;
    const int wp   = t >> 5;
    const int lane = t & 31;
    const int g    = lane >> 2;
    const int q    = lane & 3;
    const int wml  = wp & 3;          // m-group (32 tok)
    const int wn   = wp >> 2;         // 0: s-half, 1: d-half
    const int ct   = blockIdx.x;
    const int tok0 = ct * 128;
    const int b    = ct >> 9;

    uint32_t* smu = (uint32_t*)smem;
    float*    smf = (float*)smem;

    // ---- stage A once: fp16 pairs, col-permuted ----
    for (int it = 0; it < 32; it++) {
        int idx = it * 256 + t;               // 128 rows x 64 float4
        int row = idx >> 6, j = idx & 63;     // j: float4 index (k = 4j)
        float4 v = *(const float4*)&x[((size_t)(tok0 + row)) * CC + j * 4];
        smu[A0W + row * AST + permc(2 * j)]     = pack2(v.x, v.y);
        smu[A0W + row * AST + permc(2 * j + 1)] = pack2(v.z, v.w);
    }

    // hoisted row offsets (u32 words)
    const int ar0 = (wml * 32 + g) * AST;
    const int ar1 = ar0 + 8 * AST;
    const int ar2 = ar0 + 16 * AST;
    const int ar3 = ar0 + 24 * AST;
    const int brow = (wn * 64 + g) * BSTW + 2 * q;

    for (int h = 0; h < HH; h++) {
        __syncthreads();   // prior head's w/f reads done -> biases/slab writable
        if (t < 64) {
            smf[BSW + t] = g_beff[h][t];
            smf[BDW + t] = bfx[h * DD + t];
        }
        float tmp = temperature[h];
        tmp = fminf(fmaxf(tmp, 0.5f), 5.0f);
        const float invt = __fdividef(1.0f, tmp);

        float c[2][8][4];
#pragma unroll
        for (int i = 0; i < 2; i++)
#pragma unroll
            for (int j = 0; j < 8; j++)
#pragma unroll
                for (int e = 0; e < 4; e++) c[i][j][e] = 0.0f;

        const uint32_t* img = g_Bh + (size_t)h * 128 * 128;

        // ============ GEMM1: two K-halves of 128 (8 k16 steps each) ============
#pragma unroll
        for (int kh = 0; kh < 2; kh++) {
            if (kh) __syncthreads();          // slab reads done before restage
            // stage B slab [128 n][64 u32]
#pragma unroll
            for (int it = 0; it < 8; it++) {
                int idx = it * 256 + t;       // 128 rows x 16 uint4
                int row = idx >> 4, c4 = idx & 15;
                uint4 v = *(const uint4*)&img[(size_t)row * 128 + kh * 64 + c4 * 4];
                *(uint4*)&smu[B0W + row * BSTW + c4 * 4] = v;
            }
            __syncthreads();

#pragma unroll
            for (int ks = 0; ks < 8; ks++) {
                const int kca = kh * 64 + ks * 8 + 2 * q;   // A u32 col
                uint2 aL0 = *(const uint2*)&smu[A0W + ar0 + kca];  // a0,a2 (rows g)
                uint2 aH0 = *(const uint2*)&smu[A0W + ar1 + kca];  // a1,a3 (rows g+8)
                uint2 aL1 = *(const uint2*)&smu[A0W + ar2 + kca];
                uint2 aH1 = *(const uint2*)&smu[A0W + ar3 + kca];
#pragma unroll
                for (int nt = 0; nt < 8; nt++) {
                    uint2 bb = *(const uint2*)&smu[B0W + brow + nt * 8 * BSTW + ks * 8];
                    mma_f16(c[0][nt], aL0.x, aH0.x, aL0.y, aH0.y, bb.x, bb.y);
                    mma_f16(c[1][nt], aL1.x, aH1.x, aL1.y, aH1.y, bb.x, bb.y);
                }
            }
        }
        __syncthreads();   // slab reads done -> w/f stores may overwrite

        // ============ softmax (s-half -> w) / bias+store (d-half -> f) ============
        float nacc[16];
#pragma unroll
        for (int i = 0; i < 16; i++) nacc[i] = 0.0f;

        if (wn == 0) {
            const float* bs = &smf[BSW];
#pragma unroll
            for (int mt = 0; mt < 2; mt++)
#pragma unroll
                for (int rr = 0; rr < 2; rr++) {
                    const int tok = wml * 32 + mt * 16 + g + 8 * rr;
                    const int scol = (tok >> 1 & ~7) | permc(tok >> 1 & 7);
                    const int hb = tok & 1;
                    float pv[16];
                    float mx = -1e30f;
#pragma unroll
                    for (int nt = 0; nt < 8; nt++)
#pragma unroll
                        for (int e = 0; e < 2; e++) {
                            float p = (c[mt][nt][rr * 2 + e] + bs[nt * 8 + 2 * q + e]) * invt;
                            pv[nt * 2 + e] = p;
                            mx = fmaxf(mx, p);
                        }
                    mx = fmaxf(mx, __shfl_xor_sync(0xffffffffu, mx, 1));
                    mx = fmaxf(mx, __shfl_xor_sync(0xffffffffu, mx, 2));
                    float sv = 0.0f;
#pragma unroll
                    for (int j = 0; j < 16; j++) { pv[j] = __expf(pv[j] - mx); sv += pv[j]; }
                    sv += __shfl_xor_sync(0xffffffffu, sv, 1);
                    sv += __shfl_xor_sync(0xffffffffu, sv, 2);
                    const float r = __fdividef(1.0f, sv);
#pragma unroll
                    for (int nt = 0; nt < 8; nt++)
#pragma unroll
                        for (int e = 0; e < 2; e++) {
                            float wv = pv[nt * 2 + e] * r;
                            nacc[nt * 2 + e] += wv;
                            int s = nt * 8 + 2 * q + e;
                            *(__half*)((char*)smem + (W0W + s * BSTW + scol) * 4 + hb * 2) =
                                __float2half_rn(wv);
                        }
                }
        } else {
            const float* bd = &smf[BDW];
#pragma unroll
            for (int mt = 0; mt < 2; mt++)
#pragma unroll
                for (int rr = 0; rr < 2; rr++) {
                    const int tok = wml * 32 + mt * 16 + g + 8 * rr;
                    const int scol = (tok >> 1 & ~7) | permc(tok >> 1 & 7);
                    const int hb = tok & 1;
#pragma unroll
                    for (int nt = 0; nt < 8; nt++)
#pragma unroll
                        for (int e = 0; e < 2; e++) {
                            int d = nt * 8 + 2 * q + e;
                            *(__half*)((char*)smem + (F0W + d * BSTW + scol) * 4 + hb * 2) =
                                __float2half_rn(c[mt][nt][rr * 2 + e] + bd[d]);
                        }
                }
        }
        __syncthreads();

        // ============ rank update: acc[64 s][64 d] += w^T @ fx (8 k16 = 128 tok) ============
        {
            const int wm2 = wp & 3;    // s16 tile
            const int wn2 = wp >> 2;   // d32 group
            float racc[4][4];
#pragma unroll
            for (int i = 0; i < 4; i++)
#pragma unroll
                for (int j = 0; j < 4; j++) racc[i][j] = 0.0f;

#pragma unroll
            for (int ks = 0; ks < 8; ks++) {
                const int kc = ks * 8 + 2 * q;
                const int r0 = wm2 * 16 + g;
                uint2 lo = *(const uint2*)&smu[W0W + r0 * BSTW + kc];
                uint2 hi = *(const uint2*)&smu[W0W + (r0 + 8) * BSTW + kc];
#pragma unroll
                for (int nt = 0; nt < 4; nt++) {
                    uint2 bb = *(const uint2*)&smu[F0W + (wn2 * 32 + nt * 8 + g) * BSTW + kc];
                    mma_f16(racc[nt], lo.x, hi.x, lo.y, hi.y, bb.x, bb.y);
                }
            }

            const int abase = (b * HH + h) * SS;
#pragma unroll
            for (int nt = 0; nt < 4; nt++)
#pragma unroll
                for (int rr = 0; rr < 2; rr++)
#pragma unroll
                    for (int e = 0; e < 2; e++) {
                        int s = wm2 * 16 + g + 8 * rr;
                        int d = wn2 * 32 + nt * 8 + 2 * q + e;
                        atomicAdd(&g_acc[(abase + s) * DD + d], racc[nt][rr * 2 + e]);
                    }
        }

        // ---- norm reduce + atomics (s-half warps) ----
        if (wn == 0) {
#pragma unroll
            for (int j = 0; j < 16; j++) {
                nacc[j] += __shfl_xor_sync(0xffffffffu, nacc[j], 4);
                nacc[j] += __shfl_xor_sync(0xffffffffu, nacc[j], 8);
                nacc[j] += __shfl_xor_sync(0xffffffffu, nacc[j], 16);
            }
            if (g == 0) {
                const int nb = (b * HH + h) * SS;
#pragma unroll
                for (int nt = 0; nt < 8; nt++)
#pragma unroll
                    for (int e = 0; e < 2; e++)
                        atomicAdd(&g_norm[nb + nt * 8 + 2 * q + e], nacc[nt * 2 + e]);
            }
        }
    }
}

// ------------------------------------------------------------ finalize
__global__ void finalize_kernel(float* __restrict__ out) {
    int i = blockIdx.x * blockDim.x + threadIdx.x;
    if (i < BB * HH * SS * DD)
        out[i] = g_acc[i] / (g_norm[i >> 6] + 0.01f);
}

// -------------------------------------------------------------- launch
extern "C" void kernel_launch(void* const* d_in, const int* in_sizes, int n_in,
                              void* d_out, int out_size) {
    const float* x           = (const float*)d_in[0];
    const float* Wx          = (const float*)d_in[1];
    const float* bx          = (const float*)d_in[2];
    const float* Wfx         = (const float*)d_in[3];
    const float* bfx         = (const float*)d_in[4];
    const float* Wslice      = (const float*)d_in[5];
    const float* bslice      = (const float*)d_in[6];
    const float* temperature = (const float*)d_in[7];
    float* out = (float*)d_out;

    cudaFuncSetAttribute(fused_main, cudaFuncAttributeMaxDynamicSharedMemorySize,
                         SMEM_TOTAL);

    zero_kernel<<<(BB * HH * SS * DD + 255) / 256, 256>>>();
    precompute_kernel<<<HH * CC + 1, 64>>>(Wx, bx, Wslice, bslice);
    build_bt<<<HH, 256>>>(Wfx);
    fused_main<<<NCTA, 256, SMEM_TOTAL>>>(x, bfx, temperature);
    finalize_kernel<<<(BB * HH * SS * DD + 255) / 256, 256>>>(out);
}

// round 16
// speedup vs baseline: 2.2924x; 1.1199x over previous
#include <cuda_runtime.h>
#include <cuda_bf16.h>
#include <cuda_fp16.h>
#include <cstdint>

// Problem constants
#define BB 2
#define NN 65536
#define CC 256
#define HH 8
#define DD 64
#define SS 64
#define INNERD 512
#define NTOK (BB * NN)      // 131072
#define NCTA (NTOK / 128)   // 1024

// smem byte offsets. Row strides: A=528B (132 w), B/w/f=272B (68 w) — both ==4 mod 32 words,
// conflict-free for ldmatrix 8-lane x 16B phases (R6-proven).
#define ABR 528
#define BBR 272
#define A0B 0                          // A: 128 x 528 = 67584
#define BSB 67584                      // B slab: 128 x 272 = 34816
#define W0B BSB                        // w aliases slab (64 x 272)
#define F0B (BSB + 64 * BBR)           // 84992
#define BIASS (BSB + 34816)            // 102400: beff[64] f32
#define BIASD (BIASS + 256)            // bfx[64] f32
#define SMEM_TOTAL (BIASD + 256)       // 102912 bytes -> 2 CTAs/SM

// Device scratch
__device__ __align__(16) float g_Weff[HH][CC][SS];
__device__ __align__(16) float g_beff[HH][SS];
__device__ __align__(16) float g_acc[BB * HH * SS * DD];
__device__ __align__(16) float g_norm[BB * HH * SS];
__device__ __align__(16) uint32_t g_Bh[HH * 128 * 128];  // fp16x2 B^T images, natural k order

// ---------------- helpers ----------------
__device__ __forceinline__ uint32_t smem_u32(const void* p) {
    uint32_t a;
    asm("{ .reg .u64 t; cvta.to.shared.u64 t, %1; cvt.u32.u64 %0, t; }" : "=r"(a) : "l"(p));
    return a;
}
__device__ __forceinline__ void ldsm4(uint32_t* r, uint32_t addr) {
    asm volatile("ldmatrix.sync.aligned.m8n8.x4.shared.b16 {%0,%1,%2,%3}, [%4];"
                 : "=r"(r[0]), "=r"(r[1]), "=r"(r[2]), "=r"(r[3]) : "r"(addr));
}
__device__ __forceinline__ void mma_f16(float* c, uint32_t a0, uint32_t a1,
                                        uint32_t a2, uint32_t a3,
                                        uint32_t b0, uint32_t b1) {
    asm volatile(
        "mma.sync.aligned.m16n8k16.row.col.f32.f16.f16.f32 "
        "{%0,%1,%2,%3}, {%4,%5,%6,%7}, {%8,%9}, {%0,%1,%2,%3};"
        : "+f"(c[0]), "+f"(c[1]), "+f"(c[2]), "+f"(c[3])
        : "r"(a0), "r"(a1), "r"(a2), "r"(a3), "r"(b0), "r"(b1));
}
__device__ __forceinline__ uint32_t pack2(float lo, float hi) {
    __half2 h = __floats2half2_rn(lo, hi);
    return *reinterpret_cast<uint32_t*>(&h);
}

// ---------------------------------------------------------------- zero
__global__ void zero_kernel() {
    int i = blockIdx.x * blockDim.x + threadIdx.x;
    if (i < BB * HH * SS * DD) g_acc[i] = 0.0f;
    if (i < BB * HH * SS)      g_norm[i] = 0.0f;
}

// ------------------------------------------------- precompute Weff/beff
__global__ void precompute_kernel(const float* __restrict__ Wx,
                                  const float* __restrict__ bx,
                                  const float* __restrict__ Wslice,
                                  const float* __restrict__ bslice) {
    int m = blockIdx.x;
    int s = threadIdx.x;
    if (m < HH * CC) {
        int h = m / CC, k = m % CC;
        float a = 0.0f;
#pragma unroll 16
        for (int d = 0; d < DD; d++)
            a += Wx[(size_t)k * INNERD + h * DD + d] * Wslice[d * SS + s];
        g_Weff[h][k][s] = a;
    } else {
        for (int h = 0; h < HH; h++) {
            float a = bslice[s];
            for (int d = 0; d < DD; d++)
                a += bx[h * DD + d] * Wslice[d * SS + s];
            g_beff[h][s] = a;
        }
    }
}

// ---- B^T images [h][n(64 s | 64 d)][128 u32], fp16 pairs, natural k order
__global__ void build_bt(const float* __restrict__ Wfx) {
    int h = blockIdx.x;
    for (int i = threadIdx.x; i < 128 * 128; i += 256) {
        int n = i >> 7, c = i & 127;
        float v0, v1;
        if (n < 64) {
            v0 = g_Weff[h][2 * c][n];
            v1 = g_Weff[h][2 * c + 1][n];
        } else {
            v0 = Wfx[(size_t)(2 * c)     * INNERD + h * DD + (n - 64)];
            v1 = Wfx[(size_t)(2 * c + 1) * INNERD + h * DD + (n - 64)];
        }
        g_Bh[(h * 128 + n) * 128 + c] = pack2(v0, v1);
    }
}

// ---------------------------------------------------------------- main
extern __shared__ unsigned char smem[];

__global__ __launch_bounds__(256, 2) void fused_main(
    const float* __restrict__ x,
    const float* __restrict__ bfx,
    const float* __restrict__ temperature)
{
    const uint32_t smb = smem_u32(smem);
    const int t    = threadIdx.x;
    const int wp   = t >> 5;
    const int lane = t & 31;
    const int g    = lane >> 2;
    const int q    = lane & 3;
    const int wml  = wp & 3;          // m-group (32 tok)
    const int wn   = wp >> 2;         // 0: s-half, 1: d-half
    const int ct   = blockIdx.x;
    const int tok0 = ct * 128;
    const int b    = ct >> 9;

    uint32_t* smu = (uint32_t*)smem;
    float*    smf = (float*)smem;

    // ldmatrix lane-address components (R6-proven conventions)
    const int a_row  = (lane & 7) + ((lane >> 3) & 1) * 8;
    const int a_k16b = (lane >> 4) * 16;
    const int b_row  = (lane & 7) + (lane >> 4) * 8;
    const int b_k16b = ((lane >> 3) & 1) * 16;

    // ---- stage A once: fp16 pairs, natural order ----
    for (int it = 0; it < 32; it++) {
        int idx = it * 256 + t;               // 128 rows x 64 float4
        int row = idx >> 6, j = idx & 63;
        float4 v = *(const float4*)&x[((size_t)(tok0 + row)) * CC + j * 4];
        uint2 pv;
        pv.x = pack2(v.x, v.y);
        pv.y = pack2(v.z, v.w);
        *(uint2*)&smu[(A0B / 4) + row * 132 + 2 * j] = pv;
    }

    // hoisted ldmatrix base addresses
    const uint32_t aBase = smb + A0B + (wml * 32 + a_row) * ABR + a_k16b;  // +mt*16*ABR +kk*32
    const uint32_t bBase = smb + BSB + (wn * 64 + b_row) * BBR + b_k16b;   // +nt16*16*BBR +ks*32
    const uint32_t wBase = smb + W0B + ((wp & 3) * 16 + a_row) * BBR + a_k16b;
    const uint32_t fBase = smb + F0B + ((wp >> 2) * 32 + b_row) * BBR + b_k16b;

    for (int h = 0; h < HH; h++) {
        __syncthreads();   // prior head's w/f reads done -> slab/bias writable
        if (t < 64) {
            smf[BIASS / 4 + t] = g_beff[h][t];
            smf[BIASD / 4 + t] = bfx[h * DD + t];
        }
        float tmp = temperature[h];
        tmp = fminf(fmaxf(tmp, 0.5f), 5.0f);
        const float invt = __fdividef(1.0f, tmp);

        float c[2][8][4];
#pragma unroll
        for (int i = 0; i < 2; i++)
#pragma unroll
            for (int j = 0; j < 8; j++)
#pragma unroll
                for (int e = 0; e < 4; e++) c[i][j][e] = 0.0f;

        const uint32_t* img = g_Bh + (size_t)h * 128 * 128;

        // ============ GEMM1: two K-halves of 128 (8 k16 steps each) ============
#pragma unroll
        for (int kh = 0; kh < 2; kh++) {
            if (kh) __syncthreads();
            // stage B slab [128 n][64 u32]
#pragma unroll
            for (int it = 0; it < 8; it++) {
                int idx = it * 256 + t;       // 128 rows x 16 uint4
                int row = idx >> 4, c4 = idx & 15;
                uint4 v = *(const uint4*)&img[(size_t)row * 128 + kh * 64 + c4 * 4];
                *(uint4*)&smu[(BSB / 4) + row * 68 + c4 * 4] = v;
            }
            __syncthreads();

#pragma unroll
            for (int ks = 0; ks < 8; ks++) {
                const int akk = (kh * 8 + ks) * 32;
                uint32_t a0[4], a1[4];
                ldsm4(a0, aBase + akk);
                ldsm4(a1, aBase + 16 * ABR + akk);
                uint32_t bh[16];
#pragma unroll
                for (int np = 0; np < 4; np++)
                    ldsm4(&bh[np * 4], bBase + np * 16 * BBR + ks * 32);
#pragma unroll
                for (int nt = 0; nt < 8; nt++) {
                    mma_f16(c[0][nt], a0[0], a0[1], a0[2], a0[3],
                            bh[nt * 2], bh[nt * 2 + 1]);
                    mma_f16(c[1][nt], a1[0], a1[1], a1[2], a1[3],
                            bh[nt * 2], bh[nt * 2 + 1]);
                }
            }
        }
        __syncthreads();   // slab reads done -> w/f stores may overwrite

        // ============ softmax (s-half -> w) / bias+store (d-half -> f) ============
        float nacc[16];
#pragma unroll
        for (int i = 0; i < 16; i++) nacc[i] = 0.0f;

        if (wn == 0) {
            const float* bs = &smf[BIASS / 4];
#pragma unroll
            for (int mt = 0; mt < 2; mt++)
#pragma unroll
                for (int rr = 0; rr < 2; rr++) {
                    const int tok = wml * 32 + mt * 16 + g + 8 * rr;
                    float pv[16];
                    float mx = -1e30f;
#pragma unroll
                    for (int nt = 0; nt < 8; nt++)
#pragma unroll
                        for (int e = 0; e < 2; e++) {
                            float p = (c[mt][nt][rr * 2 + e] + bs[nt * 8 + 2 * q + e]) * invt;
                            pv[nt * 2 + e] = p;
                            mx = fmaxf(mx, p);
                        }
                    mx = fmaxf(mx, __shfl_xor_sync(0xffffffffu, mx, 1));
                    mx = fmaxf(mx, __shfl_xor_sync(0xffffffffu, mx, 2));
                    float sv = 0.0f;
#pragma unroll
                    for (int j = 0; j < 16; j++) { pv[j] = __expf(pv[j] - mx); sv += pv[j]; }
                    sv += __shfl_xor_sync(0xffffffffu, sv, 1);
                    sv += __shfl_xor_sync(0xffffffffu, sv, 2);
                    const float r = __fdividef(1.0f, sv);
#pragma unroll
                    for (int nt = 0; nt < 8; nt++)
#pragma unroll
                        for (int e = 0; e < 2; e++) {
                            float wv = pv[nt * 2 + e] * r;
                            nacc[nt * 2 + e] += wv;
                            int s = nt * 8 + 2 * q + e;
                            *(__half*)(smem + W0B + s * BBR + tok * 2) = __float2half_rn(wv);
                        }
                }
        } else {
            const float* bd = &smf[BIASD / 4];
#pragma unroll
            for (int mt = 0; mt < 2; mt++)
#pragma unroll
                for (int rr = 0; rr < 2; rr++) {
                    const int tok = wml * 32 + mt * 16 + g + 8 * rr;
#pragma unroll
                    for (int nt = 0; nt < 8; nt++)
#pragma unroll
                        for (int e = 0; e < 2; e++) {
                            int d = nt * 8 + 2 * q + e;
                            *(__half*)(smem + F0B + d * BBR + tok * 2) =
                                __float2half_rn(c[mt][nt][rr * 2 + e] + bd[d]);
                        }
                }
        }
        __syncthreads();

        // ============ rank update: acc[64 s][64 d] += w^T @ fx (8 k16 = 128 tok) ============
        {
            float racc[4][4];
#pragma unroll
            for (int i = 0; i < 4; i++)
#pragma unroll
                for (int j = 0; j < 4; j++) racc[i][j] = 0.0f;

#pragma unroll
            for (int ks = 0; ks < 8; ks++) {
                uint32_t aw[4], bh[8];
                ldsm4(aw, wBase + ks * 32);
                ldsm4(&bh[0], fBase + ks * 32);
                ldsm4(&bh[4], fBase + 16 * BBR + ks * 32);
#pragma unroll
                for (int nt = 0; nt < 4; nt++)
                    mma_f16(racc[nt], aw[0], aw[1], aw[2], aw[3],
                            bh[nt * 2], bh[nt * 2 + 1]);
            }

            const int abase = (b * HH + h) * SS;
            const int wm2 = wp & 3, wn2 = wp >> 2;
#pragma unroll
            for (int nt = 0; nt < 4; nt++)
#pragma unroll
                for (int rr = 0; rr < 2; rr++)
#pragma unroll
                    for (int e = 0; e < 2; e++) {
                        int s = wm2 * 16 + g + 8 * rr;
                        int d = wn2 * 32 + nt * 8 + 2 * q + e;
                        atomicAdd(&g_acc[(abase + s) * DD + d], racc[nt][rr * 2 + e]);
                    }
        }

        // ---- norm reduce + atomics (s-half warps) ----
        if (wn == 0) {
#pragma unroll
            for (int j = 0; j < 16; j++) {
                nacc[j] += __shfl_xor_sync(0xffffffffu, nacc[j], 4);
                nacc[j] += __shfl_xor_sync(0xffffffffu, nacc[j], 8);
                nacc[j] += __shfl_xor_sync(0xffffffffu, nacc[j], 16);
            }
            if (g == 0) {
                const int nb = (b * HH + h) * SS;
#pragma unroll
                for (int nt = 0; nt < 8; nt++)
#pragma unroll
                    for (int e = 0; e < 2; e++)
                        atomicAdd(&g_norm[nb + nt * 8 + 2 * q + e], nacc[nt * 2 + e]);
            }
        }
    }
}

// ------------------------------------------------------------ finalize
__global__ void finalize_kernel(float* __restrict__ out) {
    int i = blockIdx.x * blockDim.x + threadIdx.x;
    if (i < BB * HH * SS * DD)
        out[i] = g_acc[i] / (g_norm[i >> 6] + 0.01f);
}

// -------------------------------------------------------------- launch
extern "C" void kernel_launch(void* const* d_in, const int* in_sizes, int n_in,
                              void* d_out, int out_size) {
    const float* x           = (const float*)d_in[0];
    const float* Wx          = (const float*)d_in[1];
    const float* bx          = (const float*)d_in[2];
    const float* Wfx         = (const float*)d_in[3];
    const float* bfx         = (const float*)d_in[4];
    const float* Wslice      = (const float*)d_in[5];
    const float* bslice      = (const float*)d_in[6];
    const float* temperature = (const float*)d_in[7];
    float* out = (float*)d_out;

    cudaFuncSetAttribute(fused_main, cudaFuncAttributeMaxDynamicSharedMemorySize,
                         SMEM_TOTAL);

    zero_kernel<<<(BB * HH * SS * DD + 255) / 256, 256>>>();
    precompute_kernel<<<HH * CC + 1, 64>>>(Wx, bx, Wslice, bslice);
    build_bt<<<HH, 256>>>(Wfx);
    fused_main<<<NCTA, 256, SMEM_TOTAL>>>(x, bfx, temperature);
    finalize_kernel<<<(BB * HH * SS * DD + 255) / 256, 256>>>(out);
}